// round 3
// baseline (speedup 1.0000x reference)
#include <cuda_runtime.h>
#include <cuda_bf16.h>

#define NN 100000
#define NE 3200000

typedef unsigned long long ull;

// ---------------- scratch (static device arrays; no allocs) ----------------
__device__ int   g_is64;
__device__ int   g_hist[NN];
__device__ int   g_rowptr[NN + 1];
__device__ int   g_cursor[NN];
__device__ int   g_src[NE];
__device__ int   g_dst[NE];
__device__ int   g_col[NE];
__device__ int   g_part[256];
__device__ float g_dinv[NN];
__device__ float g_h0s[NN * 16];   // dinv-scaled x@W1
__device__ float g_x1 [NN * 16];   // relu layer-1 output (raw)
__device__ float g_h1s[NN * 16];   // dinv-scaled x1@W2
__device__ float g_x2 [NN * 16];   // relu layer-2 output (raw)
__device__ float g_hs [NN * 16];   // dinv-scaled JK output

// ---------------- helpers ----------------
__device__ __forceinline__ float sigf(float x) {
    return __fdividef(1.f, 1.f + __expf(-x));
}
__device__ __forceinline__ float tanh_fast(float x) {
    return __fdividef(2.f, 1.f + __expf(-2.f * x)) - 1.f;
}
__device__ __forceinline__ ull fma2(ull a, ull b, ull c) {
    ull d;
    asm("fma.rn.f32x2 %0, %1, %2, %3;" : "=l"(d) : "l"(a), "l"(b), "l"(c));
    return d;
}
__device__ __forceinline__ ull pack2(float a, float b) {
    ull r;
    asm("mov.b64 %0, {%1, %2};" : "=l"(r) : "f"(a), "f"(b));
    return r;
}
__device__ __forceinline__ float2 unpack2(ull v) {
    float2 r;
    asm("mov.b64 {%0, %1}, %2;" : "=f"(r.x), "=f"(r.y) : "l"(v));
    return r;
}

// ---------------- 1) edge dtype detection ----------------
// Node ids < 1e5, so int64 storage -> every odd 32-bit word is 0.
// If int32, odd words are random node indices (P(all 8192 sampled zero) ~ 0).
__global__ void k_detect(const unsigned* __restrict__ e) {
    __shared__ int found;
    if (threadIdx.x == 0) found = 0;
    __syncthreads();
    int f = 0;
    for (int i = threadIdx.x; i < 8192; i += 256)
        f |= (e[2 * i + 1] != 0u);
    if (f) atomicOr(&found, 1);
    __syncthreads();
    if (threadIdx.x == 0) g_is64 = found ? 0 : 1;
}

__global__ void k_zero() {
    int i = blockIdx.x * 256 + threadIdx.x;
    if (i < NN) g_hist[i] = 0;
}

// ---------------- 2) degree histogram + edge convert ----------------
__global__ void k_deg(const void* __restrict__ edges) {
    int e = blockIdx.x * 256 + threadIdx.x;
    int s, d;
    if (g_is64) {
        const long long* p = (const long long*)edges;
        s = (int)p[e];
        d = (int)p[e + NE];
    } else {
        const int* p = (const int*)edges;
        s = p[e];
        d = p[e + NE];
    }
    g_src[e] = s;
    g_dst[e] = d;
    atomicAdd(&g_hist[d], 1);
}

// ---------------- 3) scan hist -> rowptr, dinv ----------------
__global__ void k_part() {
    __shared__ int sh[512];
    int t = threadIdx.x;
    int i = blockIdx.x * 512 + t;
    int v = (i < NN) ? g_hist[i] : 0;
    if (i < NN) g_dinv[i] = rsqrtf((float)v + 1.0f);
    sh[t] = v;
    __syncthreads();
    for (int off = 256; off > 0; off >>= 1) {
        if (t < off) sh[t] += sh[t + off];
        __syncthreads();
    }
    if (t == 0) g_part[blockIdx.x] = sh[0];
}

__global__ void k_scanpart() {
    __shared__ int sh[256];
    int t = threadIdx.x;
    int v = (t < 196) ? g_part[t] : 0;
    sh[t] = v;
    __syncthreads();
    for (int off = 1; off < 256; off <<= 1) {
        int add = (t >= off) ? sh[t - off] : 0;
        __syncthreads();
        sh[t] += add;
        __syncthreads();
    }
    if (t < 196) g_part[t] = sh[t] - v;   // exclusive
    if (t == 0) g_rowptr[NN] = NE;
}

__global__ void k_rowptr() {
    __shared__ int sh[512];
    int t = threadIdx.x;
    int i = blockIdx.x * 512 + t;
    int v = (i < NN) ? g_hist[i] : 0;
    sh[t] = v;
    __syncthreads();
    for (int off = 1; off < 512; off <<= 1) {
        int add = (t >= off) ? sh[t - off] : 0;
        __syncthreads();
        sh[t] += add;
        __syncthreads();
    }
    int excl = sh[t] - v + g_part[blockIdx.x];
    if (i < NN) {
        g_rowptr[i] = excl;
        g_cursor[i] = excl;
    }
}

// ---------------- 4) scatter edges into CSR (keyed by dst) ----------------
__global__ void k_scatter() {
    int e = blockIdx.x * 256 + threadIdx.x;
    int d = g_dst[e];
    int pos = atomicAdd(&g_cursor[d], 1);
    g_col[pos] = g_src[e];
}

// ---------------- 5) h0s = dinv[v] * (x @ W1) ----------------
__global__ void __launch_bounds__(256) k_xw1(const float* __restrict__ x,
                                             const float* __restrict__ W1) {
    __shared__ __align__(16) float Wsh[512 * 16];   // 32 KB
    __shared__ __align__(16) float xsh[64 * 36];    // 64 rows x 32 k, padded
    int t = threadIdx.x;
    for (int i = t; i < 8192; i += 256) Wsh[i] = W1[i];
    int row0 = blockIdx.x * 64;
    int jq = t & 3;
    int r  = t >> 2;
    ull acc01 = 0ULL, acc23 = 0ULL;
    for (int kt = 0; kt < 512; kt += 32) {
        __syncthreads();
        for (int idx = t; idx < 512; idx += 256) {
            int rr = idx >> 3, kq = idx & 7;
            int grow = row0 + rr;
            float4 v = (grow < NN) ? *(const float4*)&x[grow * 512 + kt + kq * 4]
                                   : make_float4(0.f, 0.f, 0.f, 0.f);
            *(float4*)&xsh[rr * 36 + kq * 4] = v;
        }
        __syncthreads();
        #pragma unroll
        for (int k = 0; k < 32; k += 4) {
            float4 xv = *(float4*)&xsh[r * 36 + k];
            ulonglong2 w;
            ull p;
            w = *(ulonglong2*)&Wsh[(kt + k + 0) * 16 + jq * 4];
            p = pack2(xv.x, xv.x);
            acc01 = fma2(w.x, p, acc01); acc23 = fma2(w.y, p, acc23);
            w = *(ulonglong2*)&Wsh[(kt + k + 1) * 16 + jq * 4];
            p = pack2(xv.y, xv.y);
            acc01 = fma2(w.x, p, acc01); acc23 = fma2(w.y, p, acc23);
            w = *(ulonglong2*)&Wsh[(kt + k + 2) * 16 + jq * 4];
            p = pack2(xv.z, xv.z);
            acc01 = fma2(w.x, p, acc01); acc23 = fma2(w.y, p, acc23);
            w = *(ulonglong2*)&Wsh[(kt + k + 3) * 16 + jq * 4];
            p = pack2(xv.w, xv.w);
            acc01 = fma2(w.x, p, acc01); acc23 = fma2(w.y, p, acc23);
        }
    }
    int row = row0 + r;
    if (row < NN) {
        float dv = g_dinv[row];
        float2 a01 = unpack2(acc01), a23 = unpack2(acc23);
        float4 res;
        res.x = dv * a01.x; res.y = dv * a01.y;
        res.z = dv * a23.x; res.w = dv * a23.y;
        *(float4*)&g_h0s[row * 16 + jq * 4] = res;
    }
}

// ---------------- gather core: dinv[v] * (sum_{src->v} in[src] + in[v]) ----------
__device__ __forceinline__ float gather_sum(int v, int j, const float* __restrict__ in) {
    int b = g_rowptr[v], e = g_rowptr[v + 1];
    float acc = in[v * 16 + j];          // self-loop term (already dinv-scaled)
    int i = b;
    for (; i + 4 <= e; i += 4) {
        int s0 = g_col[i], s1 = g_col[i + 1], s2 = g_col[i + 2], s3 = g_col[i + 3];
        float v0 = in[s0 * 16 + j], v1 = in[s1 * 16 + j];
        float v2 = in[s2 * 16 + j], v3 = in[s3 * 16 + j];
        acc += (v0 + v1) + (v2 + v3);
    }
    for (; i < e; i++) acc += in[g_col[i] * 16 + j];
    return g_dinv[v] * acc;
}

// ---------------- 6) agg1 + bias + relu, fused x1@W2 ----------------
__global__ void k_agg1(const float* __restrict__ b1, const float* __restrict__ W2) {
    __shared__ float W2s[256];
    int tid = threadIdx.x;
    W2s[tid] = W2[tid];
    __syncthreads();
    int v = blockIdx.x * 16 + (tid >> 4);
    int j = tid & 15;
    float val = gather_sum(v, j, g_h0s);
    float x1v = fmaxf(val + b1[j], 0.f);
    g_x1[v * 16 + j] = x1v;
    unsigned gb = (tid & 31) & 16;
    float h1 = 0.f;
    #pragma unroll
    for (int k = 0; k < 16; k++) {
        float xk = __shfl_sync(0xffffffffu, x1v, gb + k);
        h1 = fmaf(xk, W2s[k * 16 + j], h1);
    }
    g_h1s[v * 16 + j] = g_dinv[v] * h1;
}

// ---------------- 7) agg2 + bias + relu ----------------
__global__ void k_agg2(const float* __restrict__ b2) {
    int tid = threadIdx.x;
    int v = blockIdx.x * 16 + (tid >> 4);
    int j = tid & 15;
    float val = gather_sum(v, j, g_h1s);
    g_x2[v * 16 + j] = fmaxf(val + b2[j], 0.f);
}

// ---------------- 8) JK bidirectional LSTM + attention ----------------
// Shared weight layout (transposed, j-contiguous per k):
//   [0:2048)      F w_ih^T     ws[k*128 + j] = w_ih[j][k]
//   [2048:6144)   F w_hh^T
//   [6144:8192)   B w_ih^T
//   [8192:12288)  B w_hh^T     -> exactly 48 KB
__device__ __forceinline__ void lstm_cell(
    const float* __restrict__ wih_t, const float* __restrict__ whh_t,
    const float* __restrict__ bias,
    const ull* __restrict__ xp, const ull* __restrict__ hp,
    float* __restrict__ c, float* __restrict__ hn)
{
    #pragma unroll 1
    for (int j = 0; j < 32; j += 4) {
        ull a0, a1, a2, a3, a4, a5, a6, a7;
        {
            ulonglong2 b0 = *(const ulonglong2*)(bias + 0  + j);
            ulonglong2 b1 = *(const ulonglong2*)(bias + 32 + j);
            ulonglong2 b2 = *(const ulonglong2*)(bias + 64 + j);
            ulonglong2 b3 = *(const ulonglong2*)(bias + 96 + j);
            a0 = b0.x; a1 = b0.y; a2 = b1.x; a3 = b1.y;
            a4 = b2.x; a5 = b2.y; a6 = b3.x; a7 = b3.y;
        }
        #pragma unroll
        for (int k = 0; k < 16; k++) {
            ull p = xp[k];
            const float* w = wih_t + k * 128 + j;
            ulonglong2 w0 = *(const ulonglong2*)(w);
            ulonglong2 w1 = *(const ulonglong2*)(w + 32);
            ulonglong2 w2 = *(const ulonglong2*)(w + 64);
            ulonglong2 w3 = *(const ulonglong2*)(w + 96);
            a0 = fma2(w0.x, p, a0); a1 = fma2(w0.y, p, a1);
            a2 = fma2(w1.x, p, a2); a3 = fma2(w1.y, p, a3);
            a4 = fma2(w2.x, p, a4); a5 = fma2(w2.y, p, a5);
            a6 = fma2(w3.x, p, a6); a7 = fma2(w3.y, p, a7);
        }
        #pragma unroll
        for (int k = 0; k < 32; k++) {
            ull p = hp[k];
            const float* w = whh_t + k * 128 + j;
            ulonglong2 w0 = *(const ulonglong2*)(w);
            ulonglong2 w1 = *(const ulonglong2*)(w + 32);
            ulonglong2 w2 = *(const ulonglong2*)(w + 64);
            ulonglong2 w3 = *(const ulonglong2*)(w + 96);
            a0 = fma2(w0.x, p, a0); a1 = fma2(w0.y, p, a1);
            a2 = fma2(w1.x, p, a2); a3 = fma2(w1.y, p, a3);
            a4 = fma2(w2.x, p, a4); a5 = fma2(w2.y, p, a5);
            a6 = fma2(w3.x, p, a6); a7 = fma2(w3.y, p, a7);
        }
        float2 i01 = unpack2(a0), i23 = unpack2(a1);
        float2 f01 = unpack2(a2), f23 = unpack2(a3);
        float2 g01 = unpack2(a4), g23 = unpack2(a5);
        float2 o01 = unpack2(a6), o23 = unpack2(a7);
        float iv[4] = {i01.x, i01.y, i23.x, i23.y};
        float fv[4] = {f01.x, f01.y, f23.x, f23.y};
        float gv[4] = {g01.x, g01.y, g23.x, g23.y};
        float ov[4] = {o01.x, o01.y, o23.x, o23.y};
        #pragma unroll
        for (int q = 0; q < 4; q++) {
            float cc = sigf(fv[q]) * c[j + q] + sigf(iv[q]) * tanh_fast(gv[q]);
            c[j + q] = cc;
            hn[j + q] = sigf(ov[q]) * tanh_fast(cc);
        }
    }
}

__global__ void __launch_bounds__(128)
k_lstm(const float* __restrict__ wihF, const float* __restrict__ whhF,
       const float* __restrict__ bF,
       const float* __restrict__ wihB, const float* __restrict__ whhB,
       const float* __restrict__ bB,
       const float* __restrict__ attw)
{
    __shared__ __align__(16) float ws[12288];   // exactly 48 KB
    int tid = threadIdx.x;
    for (int i = tid; i < 2048; i += 128) {
        int jj = i >> 4, kk = i & 15;
        ws[kk * 128 + jj]        = wihF[i];
        ws[6144 + kk * 128 + jj] = wihB[i];
    }
    for (int i = tid; i < 4096; i += 128) {
        int jj = i >> 5, kk = i & 31;
        ws[2048 + kk * 128 + jj] = whhF[i];
        ws[8192 + kk * 128 + jj] = whhB[i];
    }
    __syncthreads();
    int v = blockIdx.x * 128 + tid;
    if (v >= NN) return;

    const float* x1g = g_x1 + v * 16;
    const float* x2g = g_x2 + v * 16;
    ull xp[16], hp[32];
    float c[32], hn[32];
    float s0 = 0.f, s1 = 0.f;

    #pragma unroll
    for (int q = 0; q < 4; q++) {
        float4 t = *(const float4*)(x1g + 4 * q);
        xp[4 * q + 0] = pack2(t.x, t.x); xp[4 * q + 1] = pack2(t.y, t.y);
        xp[4 * q + 2] = pack2(t.z, t.z); xp[4 * q + 3] = pack2(t.w, t.w);
    }
    #pragma unroll
    for (int k = 0; k < 32; k++) { hp[k] = 0ULL; c[k] = 0.f; }

    lstm_cell(ws, ws + 2048, bF, xp, hp, c, hn);          // hf0
    #pragma unroll
    for (int k = 0; k < 32; k++) { s0 += hn[k] * attw[k]; hp[k] = pack2(hn[k], hn[k]); }

    #pragma unroll
    for (int q = 0; q < 4; q++) {
        float4 t = *(const float4*)(x2g + 4 * q);
        xp[4 * q + 0] = pack2(t.x, t.x); xp[4 * q + 1] = pack2(t.y, t.y);
        xp[4 * q + 2] = pack2(t.z, t.z); xp[4 * q + 3] = pack2(t.w, t.w);
    }
    lstm_cell(ws, ws + 2048, bF, xp, hp, c, hn);          // hf1
    #pragma unroll
    for (int k = 0; k < 32; k++) s1 += hn[k] * attw[k];

    #pragma unroll
    for (int k = 0; k < 32; k++) { hp[k] = 0ULL; c[k] = 0.f; }
    lstm_cell(ws + 6144, ws + 8192, bB, xp, hp, c, hn);   // hb1 (input x2)
    #pragma unroll
    for (int k = 0; k < 32; k++) { s1 += hn[k] * attw[32 + k]; hp[k] = pack2(hn[k], hn[k]); }

    #pragma unroll
    for (int q = 0; q < 4; q++) {
        float4 t = *(const float4*)(x1g + 4 * q);
        xp[4 * q + 0] = pack2(t.x, t.x); xp[4 * q + 1] = pack2(t.y, t.y);
        xp[4 * q + 2] = pack2(t.z, t.z); xp[4 * q + 3] = pack2(t.w, t.w);
    }
    lstm_cell(ws + 6144, ws + 8192, bB, xp, hp, c, hn);   // hb0
    #pragma unroll
    for (int k = 0; k < 32; k++) s0 += hn[k] * attw[32 + k];

    // softmax over the 2 scores (att_b cancels)
    float m = fmaxf(s0, s1);
    float e0 = __expf(s0 - m), e1 = __expf(s1 - m);
    float inv = __fdividef(1.f, e0 + e1);
    float a0 = e0 * inv, a1 = e1 * inv;
    float dv = g_dinv[v];
    float* o = g_hs + v * 16;
    #pragma unroll
    for (int q = 0; q < 4; q++) {
        float4 t1 = *(const float4*)(x1g + 4 * q);
        float4 t2 = *(const float4*)(x2g + 4 * q);
        float4 r;
        r.x = dv * (a0 * t1.x + a1 * t2.x);
        r.y = dv * (a0 * t1.y + a1 * t2.y);
        r.z = dv * (a0 * t1.z + a1 * t2.z);
        r.w = dv * (a0 * t1.w + a1 * t2.w);
        *(float4*)(o + 4 * q) = r;
    }
}

// ---------------- 9) APPNP agg + linear + log_softmax ----------------
__global__ void k_out(const float* __restrict__ linw, const float* __restrict__ linb,
                      float* __restrict__ out)
{
    __shared__ float LW[640];
    __shared__ float LB[40];
    int tid = threadIdx.x;
    for (int i = tid; i < 640; i += 256) LW[i] = linw[i];
    if (tid < 40) LB[tid] = linb[tid];
    __syncthreads();

    int v = blockIdx.x * 16 + (tid >> 4);
    int j = tid & 15;
    float hval = gather_sum(v, j, g_hs);

    unsigned gb = (tid & 31) & 16;   // lane base of this node's 16-group
    float l0 = LB[j];
    float l1 = LB[j + 16];
    float l2 = (j < 8) ? LB[j + 32] : -1e30f;
    #pragma unroll
    for (int k = 0; k < 16; k++) {
        float hk = __shfl_sync(0xffffffffu, hval, gb + k);
        l0 = fmaf(hk, LW[k * 40 + j], l0);
        l1 = fmaf(hk, LW[k * 40 + j + 16], l1);
        if (j < 8) l2 = fmaf(hk, LW[k * 40 + j + 32], l2);
    }
    // group max over the 40 logits
    float m = fmaxf(l0, l1);
    if (j < 8) m = fmaxf(m, l2);
    #pragma unroll
    for (int off = 8; off > 0; off >>= 1)
        m = fmaxf(m, __shfl_xor_sync(0xffffffffu, m, off));
    float ssum = __expf(l0 - m) + __expf(l1 - m) + ((j < 8) ? __expf(l2 - m) : 0.f);
    #pragma unroll
    for (int off = 8; off > 0; off >>= 1)
        ssum += __shfl_xor_sync(0xffffffffu, ssum, off);
    float lse = m + __logf(ssum);

    out[v * 40 + j]      = l0 - lse;
    out[v * 40 + j + 16] = l1 - lse;
    if (j < 8) out[v * 40 + j + 32] = l2 - lse;
}

// ---------------- launch ----------------
extern "C" void kernel_launch(void* const* d_in, const int* in_sizes, int n_in,
                              void* d_out, int out_size) {
    const float* x     = (const float*)d_in[0];
    const void*  edges = d_in[1];
    const float* W1    = (const float*)d_in[2];
    const float* b1    = (const float*)d_in[3];
    const float* W2    = (const float*)d_in[4];
    const float* b2    = (const float*)d_in[5];
    const float* wihF  = (const float*)d_in[6];
    const float* whhF  = (const float*)d_in[7];
    const float* bF    = (const float*)d_in[8];
    const float* wihB  = (const float*)d_in[9];
    const float* whhB  = (const float*)d_in[10];
    const float* bB    = (const float*)d_in[11];
    const float* attw  = (const float*)d_in[12];
    const float* linw  = (const float*)d_in[14];
    const float* linb  = (const float*)d_in[15];
    float* out = (float*)d_out;

    k_detect<<<1, 256>>>((const unsigned*)edges);
    k_zero<<<(NN + 255) / 256, 256>>>();
    k_deg<<<NE / 256, 256>>>(edges);
    k_part<<<196, 512>>>();
    k_scanpart<<<1, 256>>>();
    k_rowptr<<<196, 512>>>();
    k_scatter<<<NE / 256, 256>>>();
    k_xw1<<<(NN + 63) / 64, 256>>>(x, W1);
    k_agg1<<<NN / 16, 256>>>(b1, W2);
    k_agg2<<<NN / 16, 256>>>(b2);
    k_lstm<<<(NN + 127) / 128, 128>>>(wihF, whhF, bF, wihB, whhB, bB, attw);
    k_out<<<NN / 16, 256>>>(linw, linb, out);
}